// round 5
// baseline (speedup 1.0000x reference)
#include <cuda_runtime.h>

// SPHeroConv fused, R4: L1-wavefront-minimized restructure.
//  Phase A: edge-parallel sph precompute -> smem (kills 4x redundant ipos/MUFU).
//  Phase B: 16 threads per feature row (4 chunks of 16 points) -> feat gather
//           at the 2048-wavefront minimum; As stored point-major, coalesced STS.128.
//  Stage 2: GEMM 8x8 micro-tile, 4-way k-split, A read as float4 along k with
//           XOR swizzle (conflict-free), B from global (L1-resident), FFMA2.

#define BM         64
#define CDIM       64
#define FDIM       64
#define KDIM       256
#define DEG_MAX    16
#define EPC_MAX    (BM * DEG_MAX)     // 1024
#define AS2_STRIDE 260                 // 256 + 4 pad (floats)

typedef unsigned long long u64;

__device__ __forceinline__ u64 dup2f(float x) {
    u64 r; asm("mov.b64 %0, {%1, %1};" : "=l"(r) : "f"(x)); return r;
}
__device__ __forceinline__ void ffma2(u64& d, u64 a, u64 b) {
    asm("fma.rn.f32x2 %0, %1, %2, %0;" : "+l"(d) : "l"(a), "l"(b));
}
__device__ __forceinline__ float2 unpk2(u64 v) {
    float lo, hi; asm("mov.b64 {%0, %1}, %2;" : "=f"(lo), "=f"(hi) : "l"(v));
    return make_float2(lo, hi);
}

__global__ __launch_bounds__(256, 2)
void spconv_fused_kernel(const float* __restrict__ feat,      // [N_IN, 64]
                         const float* __restrict__ ipos,      // [N_IN, 3]
                         const float* __restrict__ opos,      // [N_OUT, 3]
                         const float* __restrict__ extents,   // [1]
                         const float* __restrict__ kern,      // [256, 64]
                         const float* __restrict__ bias,      // [64]
                         const int*   __restrict__ nidx,      // [E]
                         float*       __restrict__ out,       // [N_OUT, 64]
                         int nOut, int deg)
{
    extern __shared__ float smem[];
    float*  As2  = smem;                                   // [BM][AS2_STRIDE]
    float4* sphs = (float4*)(smem + BM * AS2_STRIDE);      // [EPC_MAX]
    int*    ns   = (int*)(smem + BM * AS2_STRIDE + 4 * EPC_MAX);

    const int tid = threadIdx.x;

    // ---------------- phase A: edge-parallel sph precompute ------------------
    {
        const long E_total = (long)nOut * deg;
        const int  epc     = BM * deg;
        const long cta_eb  = (long)blockIdx.x * epc;
        const float inv_ext = __fdividef(1.0f, extents[0]);

        #pragma unroll
        for (int i = 0; i < 4; i++) {
            const int el = tid + i * 256;
            if (el < epc) {
                const long ge = cta_eb + el;
                float4 sph = make_float4(0.f, 0.f, 0.f, 0.f);
                int n = 0;
                if (ge < E_total) {
                    n = nidx[ge];
                    const int pt = blockIdx.x * BM + el / deg;
                    const float ox = opos[pt * 3 + 0];
                    const float oy = opos[pt * 3 + 1];
                    const float oz = opos[pt * 3 + 2];
                    const float dx = ipos[n * 3 + 0] - ox;
                    const float dy = ipos[n * 3 + 1] - oy;
                    const float dz = ipos[n * 3 + 2] - oz;
                    const float r2p = dx * dx + dy * dy;
                    const float r2  = r2p + dz * dz;
                    const float rinv  = rsqrtf(fmaxf(r2,  1e-20f));
                    const float rpinv = rsqrtf(fmaxf(r2p, 1e-20f));
                    sph.x = (r2 * rinv) * inv_ext;
                    sph.y = dz * rinv;
                    sph.z = dy * rpinv;
                    sph.w = dx * rpinv;
                }
                sphs[el] = sph;
                ns[el]   = n;
            }
        }
    }
    __syncthreads();

    // ---------------- phase B: gather + accumulate, 16 thr/row ---------------
    // thread (prow, cq): point chunk*16+prow, channels [4cq, 4cq+4)
    const int cq   = tid & 15;
    const int prow = tid >> 4;

    #pragma unroll
    for (int chunk = 0; chunk < 4; chunk++) {
        const int ptl = chunk * 16 + prow;

        u64 g2[4][2];
        #pragma unroll
        for (int s = 0; s < 4; s++) { g2[s][0] = 0ull; g2[s][1] = 0ull; }

        const int eb = ptl * deg;
        #pragma unroll 4
        for (int k = 0; k < deg; k++) {
            const int el = eb + k;
            const int n  = ns[el];
            const float4 sph = sphs[el];
            const ulonglong2 w =
                *reinterpret_cast<const ulonglong2*>(feat + (long)n * CDIM + cq * 4);
            const u64 s0 = dup2f(sph.x), s1 = dup2f(sph.y),
                      s2 = dup2f(sph.z), s3 = dup2f(sph.w);
            ffma2(g2[0][0], s0, w.x); ffma2(g2[0][1], s0, w.y);
            ffma2(g2[1][0], s1, w.x); ffma2(g2[1][1], s1, w.y);
            ffma2(g2[2][0], s2, w.x); ffma2(g2[2][1], s2, w.y);
            ffma2(g2[3][0], s3, w.x); ffma2(g2[3][1], s3, w.y);
        }

        // coalesced STS.128: As2[ptl][ (s*64 + 4cq) ^ swz(ptl) ]
        const int swz = ((ptl >> 3) & 3) << 2;
        float* dst = As2 + ptl * AS2_STRIDE;
        #pragma unroll
        for (int s = 0; s < 4; s++) {
            const float2 f0 = unpk2(g2[s][0]);
            const float2 f1 = unpk2(g2[s][1]);
            float4 v = make_float4(f0.x, f0.y, f1.x, f1.y);
            *reinterpret_cast<float4*>(dst + ((s * CDIM + cq * 4) ^ swz)) = v;
        }
    }

    __syncthreads();

    // ---------------- stage 2: GEMM, 8x8 tile, 4-way k-split -----------------
    const int grp = tid >> 6;            // k-split group 0..3
    const int gt  = tid & 63;
    const int tr  = (gt >> 3) << 3;      // row base (point)
    const int tc  = (gt & 7) << 3;       // col base (feature)
    const int k0  = grp << 6;

    u64 acc2[8][4];
    #pragma unroll
    for (int i = 0; i < 8; i++)
        #pragma unroll
        for (int j = 0; j < 4; j++) acc2[i][j] = 0ull;

    for (int k4 = 0; k4 < 16; k4++) {
        const int kbase = k0 + k4 * 4;

        float4 a[8];
        #pragma unroll
        for (int i = 0; i < 8; i++) {
            const int r = tr + i;
            a[i] = *reinterpret_cast<const float4*>(
                As2 + r * AS2_STRIDE + (kbase ^ (((r >> 3) & 3) << 2)));
        }

        #define STEP(DK, MEM)                                                        \
        {                                                                            \
            const ulonglong2* kb =                                                   \
                reinterpret_cast<const ulonglong2*>(kern + (kbase + DK) * FDIM + tc);\
            const ulonglong2 w0 = kb[0];                                             \
            const ulonglong2 w1 = kb[1];                                             \
            _Pragma("unroll")                                                        \
            for (int i = 0; i < 8; i++) {                                            \
                const u64 ad = dup2f(a[i].MEM);                                      \
                ffma2(acc2[i][0], ad, w0.x); ffma2(acc2[i][1], ad, w0.y);            \
                ffma2(acc2[i][2], ad, w1.x); ffma2(acc2[i][3], ad, w1.y);            \
            }                                                                        \
        }
        STEP(0, x) STEP(1, y) STEP(2, z) STEP(3, w)
        #undef STEP
    }

    __syncthreads();   // all As2 reads done; reuse smem for partial tiles

    {
        float* buf = smem + grp * (BM * FDIM);
        #pragma unroll
        for (int i = 0; i < 8; i++) {
            const float2 f0 = unpk2(acc2[i][0]);
            const float2 f1 = unpk2(acc2[i][1]);
            const float2 f2 = unpk2(acc2[i][2]);
            const float2 f3 = unpk2(acc2[i][3]);
            *reinterpret_cast<float4*>(buf + (tr + i) * FDIM + tc + 0) =
                make_float4(f0.x, f0.y, f1.x, f1.y);
            *reinterpret_cast<float4*>(buf + (tr + i) * FDIM + tc + 4) =
                make_float4(f2.x, f2.y, f3.x, f3.y);
        }
    }

    __syncthreads();

    // final reduce + bias + store
    const int r  = tid >> 2;
    const int cb = (tid & 3) << 4;
    const int p  = blockIdx.x * BM + r;
    if (p < nOut) {
        #pragma unroll
        for (int j4 = 0; j4 < 16; j4 += 4) {
            float4 s0 = *reinterpret_cast<const float4*>(smem + 0 * (BM*FDIM) + r * FDIM + cb + j4);
            float4 s1 = *reinterpret_cast<const float4*>(smem + 1 * (BM*FDIM) + r * FDIM + cb + j4);
            float4 s2 = *reinterpret_cast<const float4*>(smem + 2 * (BM*FDIM) + r * FDIM + cb + j4);
            float4 s3 = *reinterpret_cast<const float4*>(smem + 3 * (BM*FDIM) + r * FDIM + cb + j4);
            float4 bb = *reinterpret_cast<const float4*>(bias + cb + j4);
            float4 v;
            v.x = s0.x + s1.x + s2.x + s3.x + bb.x;
            v.y = s0.y + s1.y + s2.y + s3.y + bb.y;
            v.z = s0.z + s1.z + s2.z + s3.z + bb.z;
            v.w = s0.w + s1.w + s2.w + s3.w + bb.w;
            *reinterpret_cast<float4*>(out + (long)p * FDIM + cb + j4) = v;
        }
    }
}

extern "C" void kernel_launch(void* const* d_in, const int* in_sizes, int n_in,
                              void* d_out, int out_size)
{
    const float* feat    = (const float*)d_in[0];
    const float* ipos    = (const float*)d_in[1];
    const float* opos    = (const float*)d_in[2];
    const float* extents = (const float*)d_in[3];
    const float* kern    = (const float*)d_in[4];
    const float* bias    = (const float*)d_in[5];
    const int*   nidx    = (const int*)d_in[6];

    float* out = (float*)d_out;

    const int nOut = in_sizes[2] / 3;
    const int deg  = in_sizes[6] / nOut;

    // smem: As2 (64*260) + sphs (1024 float4) + ns (1024 int)
    const int smemBytes = (BM * AS2_STRIDE + 4 * EPC_MAX + EPC_MAX) * (int)sizeof(float); // 87040
    cudaFuncSetAttribute(spconv_fused_kernel,
                         cudaFuncAttributeMaxDynamicSharedMemorySize, smemBytes);

    const int grid = (nOut + BM - 1) / BM;
    spconv_fused_kernel<<<grid, 256, smemBytes>>>(feat, ipos, opos, extents,
                                                  kern, bias, nidx, out, nOut, deg);
}